// round 3
// baseline (speedup 1.0000x reference)
#include <cuda_runtime.h>
#include <cuda_bf16.h>
#include <cstdint>

// DistortionLoss, O(N) per row, fully telescoped:
//   loss = inv * [ sum_{e>=1} (z_{e+1}-z_{e-1}) * P_e*(T-P_e)
//                + (1/3) * sum_i w_i^2 * (z_{i+1}-z_i) ]
//   inv = 1/(far-near), P_e = exclusive prefix of w, T = total w.
// No bins, no midpoints: near/far only enter through the final scale,
// applied once per row at lane 0 after the reduction.
//
// One warp handles TWO rows (ILP); 4 elements per lane per row.

#define FULL 0xffffffffu

__global__ __launch_bounds__(128)
void distortion_loss_kernel(const float* __restrict__ w,
                            const float* __restrict__ z,
                            const float* __restrict__ nearv,
                            const float* __restrict__ farv,
                            float* __restrict__ out,
                            int R)
{
    const int warp = (blockIdx.x * blockDim.x + threadIdx.x) >> 5;
    const int lane = threadIdx.x & 31;
    const int row0 = warp * 2;
    if (row0 >= R) return;

    // ---- front-batch ALL loads for both rows (max MLP) ----
    float4 w4[2];
    float  z0[2], z1[2], z2[2], z3[2], zedge[2];
#pragma unroll
    for (int r = 0; r < 2; ++r) {
        const int row = row0 + r;
        const float* wr = w + (size_t)row * 128;
        const float* zr = z + (size_t)row * 129;
        w4[r] = reinterpret_cast<const float4*>(wr)[lane];
        const int zi = lane * 4;
        z0[r] = __ldg(&zr[zi + 0]);
        z1[r] = __ldg(&zr[zi + 1]);
        z2[r] = __ldg(&zr[zi + 2]);
        z3[r] = __ldg(&zr[zi + 3]);
        zedge[r] = (lane == 31) ? __ldg(&zr[128]) : 0.0f;
    }
    // near/far: needed only for the final per-row scale
    const float nr0 = __ldg(&nearv[row0]);
    const float fr0 = __ldg(&farv[row0]);
    const float nr1 = __ldg(&nearv[row0 + 1]);
    const float fr1 = __ldg(&farv[row0 + 1]);

    float partial[2];

#pragma unroll
    for (int r = 0; r < 2; ++r) {
        // z4 = next lane's z0 (lane 31: the row's final element z[128])
        float z4 = __shfl_down_sync(FULL, z0[r], 1);
        if (lane == 31) z4 = zedge[r];
        // zm1 = previous lane's z3 (lane 0: garbage, killed by P=0)
        const float zm1 = __shfl_up_sync(FULL, z3[r], 1);

        // lane-local w prefixes
        const float pre1 = w4[r].x;
        const float pre2 = pre1 + w4[r].y;
        const float pre3 = pre2 + w4[r].z;
        const float wc   = pre3 + w4[r].w;

        // warp inclusive scan of lane totals
        float wInc = wc;
#pragma unroll
        for (int o = 1; o < 32; o <<= 1) {
            float t = __shfl_up_sync(FULL, wInc, o);
            if (lane >= o) wInc += t;
        }
        const float Wex = wInc - wc;                    // exclusive lane prefix
        const float T   = __shfl_sync(FULL, wInc, 31);  // row total

        // gaps z_{e+1}-z_{e-1} (computable while scan is in flight)
        const float g0 = z1[r] - zm1;
        const float g1 = z2[r] - z0[r];
        const float g2 = z3[r] - z1[r];
        const float g3 = z4    - z2[r];

        const float P0 = Wex;
        const float P1 = Wex + pre1;
        const float P2 = Wex + pre2;
        const float P3 = Wex + pre3;

        float acc;
        acc  =      g0 * (P0 * (T - P0));
        acc = fmaf(g1,  (P1 * (T - P1)), acc);
        acc = fmaf(g2,  (P2 * (T - P2)), acc);
        acc = fmaf(g3,  (P3 * (T - P3)), acc);

        // intra-bin term: sum w^2 * dz
        float intra;
        intra =      (w4[r].x * w4[r].x) * (z1[r] - z0[r]);
        intra = fmaf((w4[r].y * w4[r].y), (z2[r] - z1[r]), intra);
        intra = fmaf((w4[r].z * w4[r].z), (z3[r] - z2[r]), intra);
        intra = fmaf((w4[r].w * w4[r].w), (z4    - z3[r]), intra);

        partial[r] = fmaf(intra, (1.0f / 3.0f), acc);
    }

    // ---- butterfly reductions (both rows interleaved) ----
#pragma unroll
    for (int o = 16; o > 0; o >>= 1) {
        partial[0] += __shfl_xor_sync(FULL, partial[0], o);
        partial[1] += __shfl_xor_sync(FULL, partial[1], o);
    }

    if (lane == 0) {
        out[row0]     = partial[0] * __fdividef(1.0f, fr0 - nr0);
        out[row0 + 1] = partial[1] * __fdividef(1.0f, fr1 - nr1);
    }
}

extern "C" void kernel_launch(void* const* d_in, const int* in_sizes, int n_in,
                              void* d_out, int out_size)
{
    const float* w  = (const float*)d_in[0];   // (R, 128, 1)
    const float* z  = (const float*)d_in[1];   // (R, 129)
    const float* nr = (const float*)d_in[2];   // (R, 1)
    const float* fr = (const float*)d_in[3];   // (R, 1)
    float* out = (float*)d_out;                // (R, 1)

    const int R = in_sizes[0] / 128;
    const int threads = 128;                   // 4 warps -> 8 rows per block
    const int rowsPerBlock = (threads / 32) * 2;
    const int blocks = (R + rowsPerBlock - 1) / rowsPerBlock;
    distortion_loss_kernel<<<blocks, threads>>>(w, z, nr, fr, out, R);
}